// round 9
// baseline (speedup 1.0000x reference)
#include <cuda_runtime.h>
#include <cuda_fp16.h>

// Trilinear interpolation: fp16 channel-last scratch, 4-lane gather,
// 2 points per thread with a single 8-load inline-asm block (forced MLP 8).
//   input  d_in[0]: float32 [16, 128, 128, 128]  (C, z, y, x)
//   coords d_in[1]: float32 [1000000, 3] in [-1, 1]
//   out    d_out  : float32 [16, 1000000]

#define GS        128
#define NCH       16
#define NSPATIAL  (GS * GS * GS)
#define PAD_CELLS (GS * GS + GS + 1)   // +1 plane/row/cell for unclamped +1 corners

// fp16 scratch, zero-initialized (pad region must read as 0.0)
__device__ __align__(128) __half g_trans[(size_t)NCH * (NSPATIAL + PAD_CELLS)];

// corner byte offsets in channel-last layout: (z,y) = (0,0),(0,1),(1,0),(1,1)
#define OFF_ZY1   (GS * 32)            // 4096
#define OFF_ZY2   (GS * GS * 32)       // 524288
#define OFF_ZY3   (GS * GS * 32 + GS * 32)

__device__ __forceinline__ unsigned long long make_evict_last_policy() {
    unsigned long long pol;
    asm volatile("createpolicy.fractional.L2::evict_last.b64 %0, 1.0;" : "=l"(pol));
    return pol;
}

__device__ __forceinline__ void stg256_evict_last(void* p, unsigned long long a,
                                                  unsigned long long b,
                                                  unsigned long long c,
                                                  unsigned long long d) {
    asm volatile("st.global.L2::evict_last.v4.u64 [%0], {%1,%2,%3,%4};"
                 :: "l"(p), "l"(a), "l"(b), "l"(c), "l"(d) : "memory");
}

__global__ void __launch_bounds__(256) transpose_kernel(const float* __restrict__ in) {
    int idx = blockIdx.x * blockDim.x + threadIdx.x;
    if (idx >= NSPATIAL) return;
    __half2 v[NCH / 2];
#pragma unroll
    for (int c = 0; c < NCH; c += 2) {
        float a = __ldcs(in + (size_t)c * NSPATIAL + idx);        // streaming reads
        float b = __ldcs(in + (size_t)(c + 1) * NSPATIAL + idx);
        v[c / 2] = __floats2half2_rn(a, b);
    }
    const unsigned long long* s = reinterpret_cast<const unsigned long long*>(v);
    stg256_evict_last(g_trans + (size_t)idx * NCH, s[0], s[1], s[2], s[3]);
}

// per-point setup: lane's cell pointer + 4 (z,y) corner weights (x-weight folded in)
struct PCtx {
    const char* base;
    float w0, w1, w2, w3;
};

__device__ __forceinline__ PCtx setup_point(const float* __restrict__ coords,
                                            int n, int lane) {
    float c0 = __ldcs(coords + 3 * n + 0);
    float c1 = __ldcs(coords + 3 * n + 1);
    float c2 = __ldcs(coords + 3 * n + 2);
    // map [-1,1] -> [0,127]; +1 corners may land in the zero pad with weight 0
    float f0 = fminf(fmaxf(fmaf(c0, 63.5f, 63.5f), 0.0f), 127.0f);
    float f1 = fminf(fmaxf(fmaf(c1, 63.5f, 63.5f), 0.0f), 127.0f);
    float f2 = fminf(fmaxf(fmaf(c2, 63.5f, 63.5f), 0.0f), 127.0f);
    float fl0 = floorf(f0), fl1 = floorf(f1), fl2 = floorf(f2);
    float r0 = f0 - fl0, r1 = f1 - fl1, r2 = f2 - fl2;
    int cell00 = (((int)fl0 * GS + (int)fl1) * GS + (int)fl2);
    float wxl = (lane < 2) ? (1.0f - r2) : r2;     // lane's x-corner weight
    PCtx p;
    p.base = reinterpret_cast<const char*>(g_trans) + (size_t)cell00 * 32 + (lane & 3) * 16;
    p.w0 = (1.0f - r0) * (1.0f - r1) * wxl;
    p.w1 = (1.0f - r0) * r1 * wxl;
    p.w2 = r0 * (1.0f - r1) * wxl;
    p.w3 = r0 * r1 * wxl;
    return p;
}

__device__ __forceinline__ void fma8(float* acc, const unsigned* r, float w) {
#pragma unroll
    for (int j = 0; j < 4; j++) {
        float2 v = __half22float2(*reinterpret_cast<const __half2*>(&r[j]));
        acc[2 * j + 0] = fmaf(w, v.x, acc[2 * j + 0]);
        acc[2 * j + 1] = fmaf(w, v.y, acc[2 * j + 1]);
    }
}

__global__ void __launch_bounds__(256, 4) gather_kernel(const float* __restrict__ coords,
                                                        float* __restrict__ out,
                                                        int N) {
    int t    = blockIdx.x * blockDim.x + threadIdx.x;
    int p    = t >> 2;        // point-pair index
    int lane = t & 3;         // 0: x0/ch0-7  1: x0/ch8-15  2: x1/ch0-7  3: x1/ch8-15
    int n0   = 2 * p;
    if (n0 >= N) return;
    int  n1   = n0 + 1;
    bool has2 = (n1 < N);

    unsigned long long pol = make_evict_last_policy();

    PCtx p0 = setup_point(coords, n0, lane);
    PCtx p1 = setup_point(coords, has2 ? n1 : n0, lane);

    // ---- one asm block: all 8 corner loads issued before ANY consumption ----
    unsigned r[32];
    asm volatile(
        "ld.global.L2::cache_hint.v4.u32 {%0,%1,%2,%3},     [%32],        %34;\n\t"
        "ld.global.L2::cache_hint.v4.u32 {%4,%5,%6,%7},     [%32+4096],   %34;\n\t"
        "ld.global.L2::cache_hint.v4.u32 {%8,%9,%10,%11},   [%32+524288], %34;\n\t"
        "ld.global.L2::cache_hint.v4.u32 {%12,%13,%14,%15}, [%32+528384], %34;\n\t"
        "ld.global.L2::cache_hint.v4.u32 {%16,%17,%18,%19}, [%33],        %34;\n\t"
        "ld.global.L2::cache_hint.v4.u32 {%20,%21,%22,%23}, [%33+4096],   %34;\n\t"
        "ld.global.L2::cache_hint.v4.u32 {%24,%25,%26,%27}, [%33+524288], %34;\n\t"
        "ld.global.L2::cache_hint.v4.u32 {%28,%29,%30,%31}, [%33+528384], %34;\n\t"
        : "=r"(r[0]),  "=r"(r[1]),  "=r"(r[2]),  "=r"(r[3]),
          "=r"(r[4]),  "=r"(r[5]),  "=r"(r[6]),  "=r"(r[7]),
          "=r"(r[8]),  "=r"(r[9]),  "=r"(r[10]), "=r"(r[11]),
          "=r"(r[12]), "=r"(r[13]), "=r"(r[14]), "=r"(r[15]),
          "=r"(r[16]), "=r"(r[17]), "=r"(r[18]), "=r"(r[19]),
          "=r"(r[20]), "=r"(r[21]), "=r"(r[22]), "=r"(r[23]),
          "=r"(r[24]), "=r"(r[25]), "=r"(r[26]), "=r"(r[27]),
          "=r"(r[28]), "=r"(r[29]), "=r"(r[30]), "=r"(r[31])
        : "l"(p0.base), "l"(p1.base), "l"(pol));

    float acc0[8], acc1[8];
#pragma unroll
    for (int k = 0; k < 8; k++) { acc0[k] = 0.0f; acc1[k] = 0.0f; }

    fma8(acc0, r + 0,  p0.w0);
    fma8(acc0, r + 4,  p0.w1);
    fma8(acc0, r + 8,  p0.w2);
    fma8(acc0, r + 12, p0.w3);
    fma8(acc1, r + 16, p1.w0);
    fma8(acc1, r + 20, p1.w1);
    fma8(acc1, r + 24, p1.w2);
    fma8(acc1, r + 28, p1.w3);

    // combine x0/x1 partials: partner lane = lane^2 (same pair, always active)
    unsigned mask = __activemask();
#pragma unroll
    for (int k = 0; k < 8; k++) {
        acc0[k] += __shfl_xor_sync(mask, acc0[k], 2);
        acc1[k] += __shfl_xor_sync(mask, acc1[k], 2);
    }

    // lanes 0,2 hold final ch0-7; lanes 1,3 hold ch8-15; each stores 4 channels:
    //   lane0: ch0-3  lane2: ch4-7  lane1: ch8-11  lane3: ch12-15
    int sel    = lane >> 1;
    int chbase = (lane & 1) * 8 + sel * 4;
#pragma unroll
    for (int j = 0; j < 4; j++) {
        __stcs(out + (size_t)(chbase + j) * N + n0, acc0[sel * 4 + j]);
    }
    if (has2) {
#pragma unroll
        for (int j = 0; j < 4; j++) {
            __stcs(out + (size_t)(chbase + j) * N + n1, acc1[sel * 4 + j]);
        }
    }
}

extern "C" void kernel_launch(void* const* d_in, const int* in_sizes, int n_in,
                              void* d_out, int out_size) {
    const float* input  = (const float*)d_in[0];
    const float* coords = (const float*)d_in[1];
    float* out = (float*)d_out;
    int N = in_sizes[1] / 3;
    int pairs = (N + 1) / 2;

    transpose_kernel<<<(NSPATIAL + 255) / 256, 256>>>(input);

    long long threads = 4LL * pairs;
    int blocks = (int)((threads + 255) / 256);
    gather_kernel<<<blocks, 256>>>(coords, out, N);
}

// round 10
// speedup vs baseline: 1.0128x; 1.0128x over previous
#include <cuda_runtime.h>
#include <cuda_fp16.h>

// Trilinear interpolation: fp16 channel-last scratch + 4-lane pair gather
// + shared-memory staged, fully-coalesced output stores.
//   input  d_in[0]: float32 [16, 128, 128, 128]  (C, z, y, x)
//   coords d_in[1]: float32 [1000000, 3] in [-1, 1]
//   out    d_out  : float32 [16, 1000000]

#define GS        128
#define NCH       16
#define NSPATIAL  (GS * GS * GS)
#define PAD_CELLS (GS * GS + GS + 1)   // +1 plane/row/cell for unclamped +1 corners
#define PTS_PER_BLK 64                 // 256 threads / 4 lanes
#define SMEM_STRIDE 68                 // 64 + 4: keeps LDS.128 16B-aligned, ~conflict-free

// fp16 scratch, zero-initialized (pad region must read as 0.0)
__device__ __align__(128) __half g_trans[(size_t)NCH * (NSPATIAL + PAD_CELLS)];

__device__ __forceinline__ void stg256_evict_last(void* p, unsigned long long a,
                                                  unsigned long long b,
                                                  unsigned long long c,
                                                  unsigned long long d) {
    asm volatile("st.global.L2::evict_last.v4.u64 [%0], {%1,%2,%3,%4};"
                 :: "l"(p), "l"(a), "l"(b), "l"(c), "l"(d) : "memory");
}

__global__ void __launch_bounds__(256) transpose_kernel(const float* __restrict__ in) {
    int idx = blockIdx.x * blockDim.x + threadIdx.x;
    if (idx >= NSPATIAL) return;
    __half2 v[NCH / 2];
#pragma unroll
    for (int c = 0; c < NCH; c += 2) {
        float a = __ldcs(in + (size_t)c * NSPATIAL + idx);        // streaming reads
        float b = __ldcs(in + (size_t)(c + 1) * NSPATIAL + idx);
        v[c / 2] = __floats2half2_rn(a, b);
    }
    const unsigned long long* s = reinterpret_cast<const unsigned long long*>(v);
    stg256_evict_last(g_trans + (size_t)idx * NCH, s[0], s[1], s[2], s[3]);
}

__global__ void __launch_bounds__(256, 8) gather_kernel(const float* __restrict__ coords,
                                                        float* __restrict__ out,
                                                        int N) {
    __shared__ float s_res[NCH * SMEM_STRIDE];

    int base = blockIdx.x * PTS_PER_BLK;
    int pt   = threadIdx.x >> 2;              // point within block (0..63)
    int lane = threadIdx.x & 3;               // 0: x0/ch0-7  1: x0/ch8-15  2: x1/ch0-7  3: x1/ch8-15
    int n    = base + pt;
    int nc   = min(n, N - 1);                 // clamped for OOB threads (stores guarded later)

    float c0 = __ldcs(coords + 3 * nc + 0);
    float c1 = __ldcs(coords + 3 * nc + 1);
    float c2 = __ldcs(coords + 3 * nc + 2);
    // map [-1,1] -> [0,127], clamp in fp; +1 corners may land in the zero pad
    // but always carry weight 0 there.
    float f0 = fminf(fmaxf(fmaf(c0, 63.5f, 63.5f), 0.0f), 127.0f);
    float f1 = fminf(fmaxf(fmaf(c1, 63.5f, 63.5f), 0.0f), 127.0f);
    float f2 = fminf(fmaxf(fmaf(c2, 63.5f, 63.5f), 0.0f), 127.0f);

    float fl0 = floorf(f0), fl1 = floorf(f1), fl2 = floorf(f2);
    float r0 = f0 - fl0, r1 = f1 - fl1, r2 = f2 - fl2;

    int cell00 = (((int)fl0 * GS + (int)fl1) * GS + (int)fl2);

    float wz[2] = {1.0f - r0, r0};
    float wy[2] = {1.0f - r1, r1};
    float wxl   = (lane < 2) ? (1.0f - r2) : r2;   // this lane's x-corner weight

    const char* gbase = reinterpret_cast<const char*>(g_trans)
                      + (size_t)cell00 * 32 + lane * 16;

    float acc[8];
#pragma unroll
    for (int k = 0; k < 8; k++) acc[k] = 0.0f;

#pragma unroll
    for (int a = 0; a < 2; a++) {
#pragma unroll
        for (int b = 0; b < 2; b++) {
            float w = wz[a] * wy[b] * wxl;
            uint4 raw = __ldg(reinterpret_cast<const uint4*>(
                gbase + ((size_t)a * (GS * GS) + (size_t)b * GS) * 32));
            float2 v0 = __half22float2(*reinterpret_cast<__half2*>(&raw.x));
            float2 v1 = __half22float2(*reinterpret_cast<__half2*>(&raw.y));
            float2 v2 = __half22float2(*reinterpret_cast<__half2*>(&raw.z));
            float2 v3 = __half22float2(*reinterpret_cast<__half2*>(&raw.w));
            acc[0] = fmaf(w, v0.x, acc[0]);
            acc[1] = fmaf(w, v0.y, acc[1]);
            acc[2] = fmaf(w, v1.x, acc[2]);
            acc[3] = fmaf(w, v1.y, acc[3]);
            acc[4] = fmaf(w, v2.x, acc[4]);
            acc[5] = fmaf(w, v2.y, acc[5]);
            acc[6] = fmaf(w, v3.x, acc[6]);
            acc[7] = fmaf(w, v3.y, acc[7]);
        }
    }

    // combine x0/x1 partials: partner lane = lane^2 (same point, always active)
#pragma unroll
    for (int k = 0; k < 8; k++) {
        acc[k] += __shfl_xor_sync(0xFFFFFFFFu, acc[k], 2);
    }

    // lanes 0,2 hold final ch0-7; lanes 1,3 hold ch8-15; each lane stages 4 ch:
    //   lane0: ch0-3  lane2: ch4-7  lane1: ch8-11  lane3: ch12-15
    int sel    = lane >> 1;
    int chbase = (lane & 1) * 8 + sel * 4;
#pragma unroll
    for (int j = 0; j < 4; j++) {
        s_res[(chbase + j) * SMEM_STRIDE + pt] = acc[sel * 4 + j];
    }

    __syncthreads();

    // coalesced store phase: thread t -> channel t/16, 4-point slot t%16
    int ch   = threadIdx.x >> 4;
    int slot = (threadIdx.x & 15) * 4;
    const float4 v = *reinterpret_cast<const float4*>(&s_res[ch * SMEM_STRIDE + slot]);
    if (base + PTS_PER_BLK <= N) {
        __stcs(reinterpret_cast<float4*>(out + (size_t)ch * N + base + slot), v);
    } else {
        const float* vp = reinterpret_cast<const float*>(&v);
#pragma unroll
        for (int k = 0; k < 4; k++) {
            if (base + slot + k < N)
                __stcs(out + (size_t)ch * N + base + slot + k, vp[k]);
        }
    }
}

extern "C" void kernel_launch(void* const* d_in, const int* in_sizes, int n_in,
                              void* d_out, int out_size) {
    const float* input  = (const float*)d_in[0];
    const float* coords = (const float*)d_in[1];
    float* out = (float*)d_out;
    int N = in_sizes[1] / 3;

    transpose_kernel<<<(NSPATIAL + 255) / 256, 256>>>(input);

    int blocks = (N + PTS_PER_BLK - 1) / PTS_PER_BLK;
    gather_kernel<<<blocks, 256>>>(coords, out, N);
}

// round 11
// speedup vs baseline: 1.0757x; 1.0621x over previous
#include <cuda_runtime.h>
#include <cuda_fp16.h>

// Trilinear interpolation: fp16 channel-last scratch + 4-lane pair gather,
// persistent grid-stride loop with next-iteration coords prefetch.
//   input  d_in[0]: float32 [16, 128, 128, 128]  (C, z, y, x)
//   coords d_in[1]: float32 [1000000, 3] in [-1, 1]
//   out    d_out  : float32 [16, 1000000]

#define GS        128
#define NCH       16
#define NSPATIAL  (GS * GS * GS)
#define PAD_CELLS (GS * GS + GS + 1)   // +1 plane/row/cell for unclamped +1 corners
#define GATHER_BLOCKS 740              // 148 SMs x 5 CTAs: one persistent wave

// fp16 scratch, zero-initialized (pad region must read as 0.0)
__device__ __align__(128) __half g_trans[(size_t)NCH * (NSPATIAL + PAD_CELLS)];

__device__ __forceinline__ void stg256_evict_last(void* p, unsigned long long a,
                                                  unsigned long long b,
                                                  unsigned long long c,
                                                  unsigned long long d) {
    asm volatile("st.global.L2::evict_last.v4.u64 [%0], {%1,%2,%3,%4};"
                 :: "l"(p), "l"(a), "l"(b), "l"(c), "l"(d) : "memory");
}

__global__ void __launch_bounds__(256) transpose_kernel(const float* __restrict__ in) {
    int idx = blockIdx.x * blockDim.x + threadIdx.x;
    if (idx >= NSPATIAL) return;
    __half2 v[NCH / 2];
#pragma unroll
    for (int c = 0; c < NCH; c += 2) {
        float a = __ldcs(in + (size_t)c * NSPATIAL + idx);        // streaming reads
        float b = __ldcs(in + (size_t)(c + 1) * NSPATIAL + idx);
        v[c / 2] = __floats2half2_rn(a, b);
    }
    const unsigned long long* s = reinterpret_cast<const unsigned long long*>(v);
    stg256_evict_last(g_trans + (size_t)idx * NCH, s[0], s[1], s[2], s[3]);
}

__global__ void __launch_bounds__(256, 5) gather_kernel(const float* __restrict__ coords,
                                                        float* __restrict__ out,
                                                        int N) {
    int t      = blockIdx.x * blockDim.x + threadIdx.x;
    int lane   = t & 3;        // 0: x0/ch0-7  1: x0/ch8-15  2: x1/ch0-7  3: x1/ch8-15
    int n      = t >> 2;       // point stream start
    int stride = (gridDim.x * blockDim.x) >> 2;

    if (n >= N) return;

    // prologue: coords for the first point
    float c0 = __ldg(coords + 3 * n + 0);
    float c1 = __ldg(coords + 3 * n + 1);
    float c2 = __ldg(coords + 3 * n + 2);

    // store-slice constants: lanes 0,2 end with ch0-7; lanes 1,3 with ch8-15;
    // each lane stores 4 channels: lane0 ch0-3, lane2 ch4-7, lane1 ch8-11, lane3 ch12-15
    int sel    = lane >> 1;
    int chbase = (lane & 1) * 8 + sel * 4;
    float wsel = 0.0f;  // placeholder

    while (true) {
        // ---- setup from current coords ----
        // map [-1,1] -> [0,127], clamp in fp; +1 corners may land in the zero
        // pad with weight exactly 0.
        float f0 = fminf(fmaxf(fmaf(c0, 63.5f, 63.5f), 0.0f), 127.0f);
        float f1 = fminf(fmaxf(fmaf(c1, 63.5f, 63.5f), 0.0f), 127.0f);
        float f2 = fminf(fmaxf(fmaf(c2, 63.5f, 63.5f), 0.0f), 127.0f);

        float fl0 = floorf(f0), fl1 = floorf(f1), fl2 = floorf(f2);
        float r0 = f0 - fl0, r1 = f1 - fl1, r2 = f2 - fl2;

        int cell00 = (((int)fl0 * GS + (int)fl1) * GS + (int)fl2);

        float wxl = (lane < 2) ? (1.0f - r2) : r2;     // this lane's x weight
        float w00 = (1.0f - r0) * (1.0f - r1) * wxl;   // z0 y0
        float w01 = (1.0f - r0) * r1 * wxl;            // z0 y1
        float w10 = r0 * (1.0f - r1) * wxl;            // z1 y0
        float w11 = r0 * r1 * wxl;                     // z1 y1

        const char* base = reinterpret_cast<const char*>(g_trans)
                         + (size_t)cell00 * 32 + lane * 16;

        // ---- issue all 4 gathers (independent) ----
        uint4 g00 = __ldg(reinterpret_cast<const uint4*>(base));
        uint4 g01 = __ldg(reinterpret_cast<const uint4*>(base + GS * 32));
        uint4 g10 = __ldg(reinterpret_cast<const uint4*>(base + GS * GS * 32));
        uint4 g11 = __ldg(reinterpret_cast<const uint4*>(base + GS * GS * 32 + GS * 32));

        // ---- prefetch next iteration's coords (overlaps gather latency) ----
        int  n2   = n + stride;
        bool more = (n2 < N);
        float d0 = c0, d1 = c1, d2 = c2;
        if (more) {
            d0 = __ldg(coords + 3 * n2 + 0);
            d1 = __ldg(coords + 3 * n2 + 1);
            d2 = __ldg(coords + 3 * n2 + 2);
        }

        // ---- consume gathers ----
        float acc[8];
#pragma unroll
        for (int k = 0; k < 8; k++) acc[k] = 0.0f;

        {
            const uint4* gs[4] = {&g00, &g01, &g10, &g11};
            float        ws[4] = {w00, w01, w10, w11};
#pragma unroll
            for (int k = 0; k < 4; k++) {
                float w = ws[k];
                const unsigned* r = reinterpret_cast<const unsigned*>(gs[k]);
#pragma unroll
                for (int j = 0; j < 4; j++) {
                    float2 v = __half22float2(*reinterpret_cast<const __half2*>(&r[j]));
                    acc[2 * j + 0] = fmaf(w, v.x, acc[2 * j + 0]);
                    acc[2 * j + 1] = fmaf(w, v.y, acc[2 * j + 1]);
                }
            }
        }

        // combine x0/x1 partials: partner lane = lane^2 (same point, always active)
#pragma unroll
        for (int k = 0; k < 8; k++) {
            acc[k] += __shfl_xor_sync(0xFFFFFFFFu, acc[k], 2);
        }

        size_t nn = (size_t)n;
#pragma unroll
        for (int j = 0; j < 4; j++) {
            __stcs(out + (size_t)(chbase + j) * N + nn, acc[sel * 4 + j]);
        }

        if (!more) break;
        n = n2; c0 = d0; c1 = d1; c2 = d2;
    }
    (void)wsel;
}

extern "C" void kernel_launch(void* const* d_in, const int* in_sizes, int n_in,
                              void* d_out, int out_size) {
    const float* input  = (const float*)d_in[0];
    const float* coords = (const float*)d_in[1];
    float* out = (float*)d_out;
    int N = in_sizes[1] / 3;

    transpose_kernel<<<(NSPATIAL + 255) / 256, 256>>>(input);

    long long threads = 4LL * N;
    int maxblocks = (int)((threads + 255) / 256);
    int blocks = GATHER_BLOCKS < maxblocks ? GATHER_BLOCKS : maxblocks;
    gather_kernel<<<blocks, 256>>>(coords, out, N);
}